// round 5
// baseline (speedup 1.0000x reference)
#include <cuda_runtime.h>
#include <stdint.h>

#define D 128        // feature dim: one warp = one row (32 lanes x float4)
#define ITEMS 4      // nnz rows per warp per pass, front-batched for MLP
#define NPASS 4      // output partitions (each ~32 MB -> L2-resident atomics)

__global__ void gather_scatter_pass_kernel(const float* __restrict__ x,
                                           const void* __restrict__ from_idx,
                                           const void* __restrict__ to_idx,
                                           float* __restrict__ out,
                                           int nnz,
                                           long long num_from,
                                           long long num_to,
                                           long long t_lo,
                                           long long t_hi) {
    // Per-block index-dtype detection (int32 vs int64).
    // int64 index values are < 2^31 here, so all odd 32-bit words are 0.
    __shared__ int s_is64;
    if (threadIdx.x == 0) {
        const unsigned int* w = (const unsigned int*)from_idx;
        s_is64 = (w[1] == 0u && w[3] == 0u && w[5] == 0u && w[7] == 0u) ? 1 : 0;
    }
    __syncthreads();
    const int is64 = s_is64;

    int gtid = blockIdx.x * blockDim.x + threadIdx.x;
    int warp = gtid >> 5;
    int lane = gtid & 31;

    long long base = (long long)warp * ITEMS;
    if (base >= nnz) return;

    long long f[ITEMS], t[ITEMS];
#pragma unroll
    for (int k = 0; k < ITEMS; k++) {
        long long i = base + k;
        f[k] = -1;
        if (i < nnz) {
            long long ff, tt;
            if (is64) {
                ff = ((const long long*)from_idx)[i];
                tt = ((const long long*)to_idx)[i];
            } else {
                ff = (long long)((const int*)from_idx)[i];
                tt = (long long)((const int*)to_idx)[i];
            }
            // Select this pass's output partition; defensive bounds too.
            if (ff >= 0 && ff < num_from && tt >= t_lo && tt < t_hi) {
                f[k] = ff;
                t[k] = tt;
            }
        }
    }

    // Front-batch independent 512B gathers (MLP). __ldcs = cache-streaming
    // (evict-first): gather data is used ~2x ever; keep the hot out-partition
    // lines resident in L2 instead.
    float4 v[ITEMS];
#pragma unroll
    for (int k = 0; k < ITEMS; k++) {
        if (f[k] >= 0) {
            const float4* src = reinterpret_cast<const float4*>(x + f[k] * (long long)D);
            v[k] = __ldcs(src + lane);
        }
    }

    // Vector reductions (no return), 16B per op, land in L2-resident partition.
#pragma unroll
    for (int k = 0; k < ITEMS; k++) {
        if (f[k] >= 0) {
            float* dst = out + t[k] * (long long)D + lane * 4;
            asm volatile("red.global.add.v4.f32 [%0], {%1, %2, %3, %4};"
                         :: "l"(dst), "f"(v[k].x), "f"(v[k].y), "f"(v[k].z), "f"(v[k].w)
                         : "memory");
        }
    }
}

extern "C" void kernel_launch(void* const* d_in, const int* in_sizes, int n_in,
                              void* d_out, int out_size) {
    const float* x = (const float*)d_in[0];
    const void*  from_idx = d_in[1];
    const void*  to_idx   = d_in[2];
    float* out = (float*)d_out;

    int nnz = in_sizes[1];
    long long num_from = (long long)in_sizes[0] / D;
    long long num_to   = (long long)out_size / D;

    long long rows_per_pass = (num_to + NPASS - 1) / NPASS;

    long long nwarps = ((long long)nnz + ITEMS - 1) / ITEMS;
    long long total_threads = nwarps * 32;
    int threads = 256;
    unsigned blocks = (unsigned)((total_threads + threads - 1) / threads);

    for (int p = 0; p < NPASS; p++) {
        long long t_lo = (long long)p * rows_per_pass;
        long long t_hi = t_lo + rows_per_pass;
        if (t_hi > num_to) t_hi = num_to;
        if (t_lo >= t_hi) break;

        // Zero this partition right before its pass so the zeroed lines are
        // still L2-resident when the atomics arrive.
        cudaMemsetAsync(out + t_lo * D, 0, (size_t)(t_hi - t_lo) * D * sizeof(float));

        gather_scatter_pass_kernel<<<blocks, threads>>>(
            x, from_idx, to_idx, out, nnz, num_from, num_to, t_lo, t_hi);
    }
}

// round 6
// speedup vs baseline: 1.9113x; 1.9113x over previous
#include <cuda_runtime.h>
#include <stdint.h>

#define D 128        // feature dim: one warp = one row (32 lanes x float4)
#define NPASS 4      // output partitions (each ~32 MB -> L2-resident atomics)

__global__ void gather_scatter_pass_kernel(const float* __restrict__ x,
                                           const void* __restrict__ from_idx,
                                           const void* __restrict__ to_idx,
                                           float* __restrict__ out,
                                           int nnz,
                                           int num_from,
                                           int t_lo,
                                           int t_hi) {
    // Per-block index-dtype detection (int32 vs int64). Index values fit in
    // 32 bits, so for int64 data every odd 32-bit word is 0.
    __shared__ int s_is64;
    if (threadIdx.x == 0) {
        const unsigned int* w = (const unsigned int*)from_idx;
        s_is64 = (w[1] == 0u && w[3] == 0u && w[5] == 0u && w[7] == 0u) ? 1 : 0;
    }
    __syncthreads();
    const int is64 = s_is64;

    const int gtid = blockIdx.x * blockDim.x + threadIdx.x;
    const int lane = threadIdx.x & 31;
    const int i = gtid;  // each LANE owns one nonzero (coalesced index loads)

    int f = 0, t = -1;
    if (i < nnz) {
        if (is64) {
            f = (int)((const long long*)from_idx)[i];
            t = (int)((const long long*)to_idx)[i];
        } else {
            f = ((const int*)from_idx)[i];
            t = ((const int*)to_idx)[i];
        }
    }
    const bool match = (i < nnz) & (t >= t_lo) & (t < t_hi) & (f >= 0) & (f < num_from);
    unsigned mask = __ballot_sync(0xFFFFFFFFu, match);

    // Loop over matching items only; broadcast (f,t), whole warp moves the
    // 512B row. Two items per iteration for MLP=2 on the gather path.
    while (mask) {
        int src0 = __ffs(mask) - 1; mask &= mask - 1;
        int src1 = -1;
        if (mask) { src1 = __ffs(mask) - 1; mask &= mask - 1; }

        int f0 = __shfl_sync(0xFFFFFFFFu, f, src0);
        int t0 = __shfl_sync(0xFFFFFFFFu, t, src0);
        int f1 = __shfl_sync(0xFFFFFFFFu, f, src1 < 0 ? 0 : src1);
        int t1 = __shfl_sync(0xFFFFFFFFu, t, src1 < 0 ? 0 : src1);

        // __ldcs = streaming (evict-first): keep hot out-partition in L2.
        float4 v0 = __ldcs(reinterpret_cast<const float4*>(x + (long long)f0 * D) + lane);
        float4 v1;
        if (src1 >= 0)
            v1 = __ldcs(reinterpret_cast<const float4*>(x + (long long)f1 * D) + lane);

        float* dst0 = out + (long long)t0 * D + lane * 4;
        asm volatile("red.global.add.v4.f32 [%0], {%1, %2, %3, %4};"
                     :: "l"(dst0), "f"(v0.x), "f"(v0.y), "f"(v0.z), "f"(v0.w)
                     : "memory");
        if (src1 >= 0) {
            float* dst1 = out + (long long)t1 * D + lane * 4;
            asm volatile("red.global.add.v4.f32 [%0], {%1, %2, %3, %4};"
                         :: "l"(dst1), "f"(v1.x), "f"(v1.y), "f"(v1.z), "f"(v1.w)
                         : "memory");
        }
    }
}

extern "C" void kernel_launch(void* const* d_in, const int* in_sizes, int n_in,
                              void* d_out, int out_size) {
    const float* x = (const float*)d_in[0];
    const void*  from_idx = d_in[1];
    const void*  to_idx   = d_in[2];
    float* out = (float*)d_out;

    int nnz = in_sizes[1];
    int num_from = (int)((long long)in_sizes[0] / D);
    int num_to   = (int)((long long)out_size / D);

    int rows_per_pass = (num_to + NPASS - 1) / NPASS;

    int threads = 256;
    unsigned blocks = (unsigned)(((long long)nnz + threads - 1) / threads);

    for (int p = 0; p < NPASS; p++) {
        int t_lo = p * rows_per_pass;
        int t_hi = t_lo + rows_per_pass;
        if (t_hi > num_to) t_hi = num_to;
        if (t_lo >= t_hi) break;

        // Zero this partition right before its pass so the zeroed lines are
        // still L2-resident when the atomics arrive.
        cudaMemsetAsync(out + (long long)t_lo * D, 0,
                        (size_t)(t_hi - t_lo) * D * sizeof(float));

        gather_scatter_pass_kernel<<<blocks, threads>>>(
            x, from_idx, to_idx, out, nnz, num_from, t_lo, t_hi);
    }
}

// round 7
// speedup vs baseline: 1.9390x; 1.0145x over previous
#include <cuda_runtime.h>
#include <stdint.h>

#define D 128        // feature dim: one warp = one row (32 lanes x float4)
#define NPASS 4      // output partitions (each ~32 MB -> L2-resident atomics)

__global__ void gather_scatter_pass_kernel(const float* __restrict__ x,
                                           const void* __restrict__ from_idx,
                                           const void* __restrict__ to_idx,
                                           float* __restrict__ out,
                                           int nnz,
                                           int num_from,
                                           int t_lo,
                                           int t_hi) {
    // Per-block index-dtype detection (int32 vs int64). Index values fit in
    // 32 bits, so for int64 data every odd 32-bit word is 0.
    __shared__ int s_is64;
    if (threadIdx.x == 0) {
        const unsigned int* w = (const unsigned int*)from_idx;
        s_is64 = (w[1] == 0u && w[3] == 0u && w[5] == 0u && w[7] == 0u) ? 1 : 0;
    }
    __syncthreads();
    const int is64 = s_is64;

    const int gtid = blockIdx.x * blockDim.x + threadIdx.x;
    const int lane = threadIdx.x & 31;
    const int i = gtid;  // each LANE owns one nonzero (coalesced index loads)

    int f = 0, t = -1;
    if (i < nnz) {
        if (is64) {
            f = (int)((const long long*)from_idx)[i];
            t = (int)((const long long*)to_idx)[i];
        } else {
            f = ((const int*)from_idx)[i];
            t = ((const int*)to_idx)[i];
        }
    }
    const bool match = (i < nnz) & (t >= t_lo) & (t < t_hi) & (f >= 0) & (f < num_from);
    unsigned mask = __ballot_sync(0xFFFFFFFFu, match);

    // Loop over matching items only; broadcast (f,t), whole warp moves the
    // 512B row. FOUR items per iteration -> MLP=4 on the gather path.
    while (mask) {
        int s[4];
        s[0] = __ffs(mask) - 1; mask &= mask - 1;
        s[1] = mask ? (__ffs(mask) - 1) : -1; if (s[1] >= 0) mask &= mask - 1;
        s[2] = mask ? (__ffs(mask) - 1) : -1; if (s[2] >= 0) mask &= mask - 1;
        s[3] = mask ? (__ffs(mask) - 1) : -1; if (s[3] >= 0) mask &= mask - 1;

        int fk[4], tk[4];
#pragma unroll
        for (int k = 0; k < 4; k++) {
            int srck = s[k] < 0 ? 0 : s[k];
            fk[k] = __shfl_sync(0xFFFFFFFFu, f, srck);
            tk[k] = __shfl_sync(0xFFFFFFFFu, t, srck);
        }

        // Front-batched independent 512B gathers. __ldcs = streaming
        // (evict-first): keep the hot out-partition resident in L2.
        float4 v[4];
#pragma unroll
        for (int k = 0; k < 4; k++) {
            if (s[k] >= 0)
                v[k] = __ldcs(reinterpret_cast<const float4*>(
                                  x + (long long)fk[k] * D) + lane);
        }

        // Vector reductions (no return), 16B per op, into L2-resident partition.
#pragma unroll
        for (int k = 0; k < 4; k++) {
            if (s[k] >= 0) {
                float* dst = out + (long long)tk[k] * D + lane * 4;
                asm volatile("red.global.add.v4.f32 [%0], {%1, %2, %3, %4};"
                             :: "l"(dst), "f"(v[k].x), "f"(v[k].y), "f"(v[k].z), "f"(v[k].w)
                             : "memory");
            }
        }
    }
}

extern "C" void kernel_launch(void* const* d_in, const int* in_sizes, int n_in,
                              void* d_out, int out_size) {
    const float* x = (const float*)d_in[0];
    const void*  from_idx = d_in[1];
    const void*  to_idx   = d_in[2];
    float* out = (float*)d_out;

    int nnz = in_sizes[1];
    int num_from = (int)((long long)in_sizes[0] / D);
    int num_to   = (int)((long long)out_size / D);

    int rows_per_pass = (num_to + NPASS - 1) / NPASS;

    int threads = 256;
    unsigned blocks = (unsigned)(((long long)nnz + threads - 1) / threads);

    for (int p = 0; p < NPASS; p++) {
        int t_lo = p * rows_per_pass;
        int t_hi = t_lo + rows_per_pass;
        if (t_hi > num_to) t_hi = num_to;
        if (t_lo >= t_hi) break;

        // Zero this partition right before its pass so the zeroed lines are
        // still L2-resident when the atomics arrive.
        cudaMemsetAsync(out + (long long)t_lo * D, 0,
                        (size_t)(t_hi - t_lo) * D * sizeof(float));

        gather_scatter_pass_kernel<<<blocks, threads>>>(
            x, from_idx, to_idx, out, nnz, num_from, t_lo, t_hi);
    }
}

// round 8
// speedup vs baseline: 2.0752x; 1.0702x over previous
#include <cuda_runtime.h>
#include <stdint.h>

#define D 128        // feature dim: one warp = one row (32 lanes x float4)
#define NPASS 2      // output partitions (each 64 MB; L2=126MB keeps it resident
                     // because the gather stream is marked evict-first)

__global__ void gather_scatter_pass_kernel(const float* __restrict__ x,
                                           const void* __restrict__ from_idx,
                                           const void* __restrict__ to_idx,
                                           float* __restrict__ out,
                                           int nnz,
                                           int num_from,
                                           int t_lo,
                                           int t_hi) {
    // Per-block index-dtype detection (int32 vs int64). Index values fit in
    // 32 bits, so for int64 data every odd 32-bit word is 0.
    __shared__ int s_is64;
    if (threadIdx.x == 0) {
        const unsigned int* w = (const unsigned int*)from_idx;
        s_is64 = (w[1] == 0u && w[3] == 0u && w[5] == 0u && w[7] == 0u) ? 1 : 0;
    }
    __syncthreads();
    const int is64 = s_is64;

    const int gtid = blockIdx.x * blockDim.x + threadIdx.x;
    const int lane = threadIdx.x & 31;
    const int i = gtid;  // each LANE owns one nonzero (coalesced index loads)

    int f = 0, t = -1;
    if (i < nnz) {
        if (is64) {
            f = (int)((const long long*)from_idx)[i];
            t = (int)((const long long*)to_idx)[i];
        } else {
            f = ((const int*)from_idx)[i];
            t = ((const int*)to_idx)[i];
        }
    }
    const bool match = (i < nnz) & (t >= t_lo) & (t < t_hi) & (f >= 0) & (f < num_from);
    unsigned mask = __ballot_sync(0xFFFFFFFFu, match);

    // Loop over matching items only; broadcast (f,t), whole warp moves the
    // 512B row. Four items per iteration -> MLP=4 on the gather path.
    while (mask) {
        int s[4];
        s[0] = __ffs(mask) - 1; mask &= mask - 1;
        s[1] = mask ? (__ffs(mask) - 1) : -1; if (s[1] >= 0) mask &= mask - 1;
        s[2] = mask ? (__ffs(mask) - 1) : -1; if (s[2] >= 0) mask &= mask - 1;
        s[3] = mask ? (__ffs(mask) - 1) : -1; if (s[3] >= 0) mask &= mask - 1;

        int fk[4], tk[4];
#pragma unroll
        for (int k = 0; k < 4; k++) {
            int srck = s[k] < 0 ? 0 : s[k];
            fk[k] = __shfl_sync(0xFFFFFFFFu, f, srck);
            tk[k] = __shfl_sync(0xFFFFFFFFu, t, srck);
        }

        // Front-batched independent 512B gathers. __ldcs = streaming
        // (evict-first): keeps the hot out-partition resident in L2.
        float4 v[4];
#pragma unroll
        for (int k = 0; k < 4; k++) {
            if (s[k] >= 0)
                v[k] = __ldcs(reinterpret_cast<const float4*>(
                                  x + (long long)fk[k] * D) + lane);
        }

        // Vector reductions (no return), 16B per op, into L2-resident partition.
#pragma unroll
        for (int k = 0; k < 4; k++) {
            if (s[k] >= 0) {
                float* dst = out + (long long)tk[k] * D + lane * 4;
                asm volatile("red.global.add.v4.f32 [%0], {%1, %2, %3, %4};"
                             :: "l"(dst), "f"(v[k].x), "f"(v[k].y), "f"(v[k].z), "f"(v[k].w)
                             : "memory");
            }
        }
    }
}

extern "C" void kernel_launch(void* const* d_in, const int* in_sizes, int n_in,
                              void* d_out, int out_size) {
    const float* x = (const float*)d_in[0];
    const void*  from_idx = d_in[1];
    const void*  to_idx   = d_in[2];
    float* out = (float*)d_out;

    int nnz = in_sizes[1];
    int num_from = (int)((long long)in_sizes[0] / D);
    int num_to   = (int)((long long)out_size / D);

    int rows_per_pass = (num_to + NPASS - 1) / NPASS;

    int threads = 256;
    unsigned blocks = (unsigned)(((long long)nnz + threads - 1) / threads);

    for (int p = 0; p < NPASS; p++) {
        int t_lo = p * rows_per_pass;
        int t_hi = t_lo + rows_per_pass;
        if (t_hi > num_to) t_hi = num_to;
        if (t_lo >= t_hi) break;

        // Zero this partition right before its pass so the zeroed lines are
        // still L2-resident when the atomics arrive.
        cudaMemsetAsync(out + (long long)t_lo * D, 0,
                        (size_t)(t_hi - t_lo) * D * sizeof(float));

        gather_scatter_pass_kernel<<<blocks, threads>>>(
            x, from_idx, to_idx, out, nnz, num_from, t_lo, t_hi);
    }
}

// round 9
// speedup vs baseline: 2.0794x; 1.0020x over previous
#include <cuda_runtime.h>
#include <stdint.h>

#define D 128        // feature dim: one warp = one row (32 lanes x float4)
#define NPASS 2      // output partitions (each 64 MB; L2=126MB keeps it resident
                     // because the gather stream is marked evict-first)

__global__ void gather_scatter_pass_kernel(const float* __restrict__ x,
                                           const void* __restrict__ from_idx,
                                           const void* __restrict__ to_idx,
                                           float* __restrict__ out,
                                           int nnz,
                                           int num_from,
                                           int t_lo,
                                           int t_hi) {
    // Per-block index-dtype detection (int32 vs int64). Index values fit in
    // 32 bits, so for int64 data every odd 32-bit word is 0.
    __shared__ int s_is64;
    if (threadIdx.x == 0) {
        const unsigned int* w = (const unsigned int*)from_idx;
        s_is64 = (w[1] == 0u && w[3] == 0u && w[5] == 0u && w[7] == 0u) ? 1 : 0;
    }
    __syncthreads();
    const int is64 = s_is64;

    const int gtid = blockIdx.x * blockDim.x + threadIdx.x;
    const int lane = threadIdx.x & 31;
    const int i = gtid;  // each LANE owns one nonzero (coalesced index loads)

    int f = 0, t = -1;
    if (i < nnz) {
        if (is64) {
            f = (int)((const long long*)from_idx)[i];
            t = (int)((const long long*)to_idx)[i];
        } else {
            f = ((const int*)from_idx)[i];
            t = ((const int*)to_idx)[i];
        }
    }
    const bool match = (i < nnz) & (t >= t_lo) & (t < t_hi) & (f >= 0) & (f < num_from);
    unsigned mask = __ballot_sync(0xFFFFFFFFu, match);

    // Loop over matching items only; broadcast (f,t), whole warp moves the
    // 512B row. Four items per iteration -> MLP=4 on the gather path.
    while (mask) {
        int s[4];
        s[0] = __ffs(mask) - 1; mask &= mask - 1;
        s[1] = mask ? (__ffs(mask) - 1) : -1; if (s[1] >= 0) mask &= mask - 1;
        s[2] = mask ? (__ffs(mask) - 1) : -1; if (s[2] >= 0) mask &= mask - 1;
        s[3] = mask ? (__ffs(mask) - 1) : -1; if (s[3] >= 0) mask &= mask - 1;

        int fk[4], tk[4];
#pragma unroll
        for (int k = 0; k < 4; k++) {
            int srck = s[k] < 0 ? 0 : s[k];
            fk[k] = __shfl_sync(0xFFFFFFFFu, f, srck);
            tk[k] = __shfl_sync(0xFFFFFFFFu, t, srck);
        }

        // Front-batched independent 512B gathers. __ldcs = streaming
        // (evict-first): keeps the hot out-partition resident in L2.
        float4 v[4];
#pragma unroll
        for (int k = 0; k < 4; k++) {
            if (s[k] >= 0)
                v[k] = __ldcs(reinterpret_cast<const float4*>(
                                  x + (long long)fk[k] * D) + lane);
        }

        // Vector reductions (no return), 16B per op, into L2-resident partition.
#pragma unroll
        for (int k = 0; k < 4; k++) {
            if (s[k] >= 0) {
                float* dst = out + (long long)tk[k] * D + lane * 4;
                asm volatile("red.global.add.v4.f32 [%0], {%1, %2, %3, %4};"
                             :: "l"(dst), "f"(v[k].x), "f"(v[k].y), "f"(v[k].z), "f"(v[k].w)
                             : "memory");
            }
        }
    }
}

extern "C" void kernel_launch(void* const* d_in, const int* in_sizes, int n_in,
                              void* d_out, int out_size) {
    const float* x = (const float*)d_in[0];
    const void*  from_idx = d_in[1];
    const void*  to_idx   = d_in[2];
    float* out = (float*)d_out;

    int nnz = in_sizes[1];
    int num_from = (int)((long long)in_sizes[0] / D);
    int num_to   = (int)((long long)out_size / D);

    int rows_per_pass = (num_to + NPASS - 1) / NPASS;

    int threads = 256;
    unsigned blocks = (unsigned)(((long long)nnz + threads - 1) / threads);

    for (int p = 0; p < NPASS; p++) {
        int t_lo = p * rows_per_pass;
        int t_hi = t_lo + rows_per_pass;
        if (t_hi > num_to) t_hi = num_to;
        if (t_lo >= t_hi) break;

        // Zero this partition right before its pass so the zeroed lines are
        // still L2-resident when the atomics arrive.
        cudaMemsetAsync(out + (long long)t_lo * D, 0,
                        (size_t)(t_hi - t_lo) * D * sizeof(float));

        gather_scatter_pass_kernel<<<blocks, threads>>>(
            x, from_idx, to_idx, out, nnz, num_from, t_lo, t_hi);
    }
}